// round 5
// baseline (speedup 1.0000x reference)
#include <cuda_runtime.h>
#include <cuda_bf16.h>
#include <math.h>
#include <stdint.h>

// LSTM T=512, B=64, I=H=512 on GB300 (sm_103a via compute_103, HMMA path).
// Phase 1 (parallel): gx[t][col][b] = x_t @ Wx + bias  (3-pass bf16 split, fp32 out)
// Phase 2 (persistent, 128 CTAs x 256 thr): per step, CTA bid computes
//   gates(:, cols {g*512 + 4bid + jj}) = gx + h @ Wh   (full K=512 in-CTA)
// then LOCAL elementwise for its 4 h-columns; ONE grid barrier per step.

#define T_STEPS 512
#define B_SZ    64
#define H_SZ    512
#define G4      2048
#define NCTA    128
#define NTHR    256

// ---------- global scratch ----------
__device__ float    g_gx[(size_t)T_STEPS * G4 * B_SZ];   // [t][col][b] fp32 (268MB)
__device__ __align__(16) __nv_bfloat16 g_h_hi[B_SZ * H_SZ];  // [b][j]
__device__ __align__(16) __nv_bfloat16 g_h_lo[B_SZ * H_SZ];
__device__ unsigned g_bar;

__device__ __forceinline__ float sigmoidf_fast(float x) {
    return 1.0f / (1.0f + __expf(-x));
}
__device__ __forceinline__ float tanhf_fast(float x) {
    return 2.0f / (1.0f + __expf(-2.0f * x)) - 1.0f;
}
__device__ __forceinline__ void mma_bf16(float* d, const uint32_t* a, const uint32_t* b) {
    asm volatile(
        "mma.sync.aligned.m16n8k16.row.col.f32.bf16.bf16.f32 "
        "{%0,%1,%2,%3}, {%4,%5,%6,%7}, {%8,%9}, {%0,%1,%2,%3};"
        : "+f"(d[0]), "+f"(d[1]), "+f"(d[2]), "+f"(d[3])
        : "r"(a[0]), "r"(a[1]), "r"(a[2]), "r"(a[3]), "r"(b[0]), "r"(b[1]));
}

// ============================================================================
// Phase 1: gx = x @ Wx + bias.  One CTA per timestep t; x_t resident in SMEM,
// W streamed from L2 in K-chunks. Tile M64 x N64 x K512, 8 warps 4M x 2N.
// ============================================================================
#define P1_ASTR 1040                     // A row stride bytes (K=512 bf16 + 16 pad)
#define P1_WSTR 528                      // W chunk row stride (K=256 bf16 + 16 pad)
#define P1_AHI  0
#define P1_ALO  (64 * P1_ASTR)           // 66560
#define P1_WHI  (2 * 64 * P1_ASTR)       // 133120
#define P1_WLO  (P1_WHI + 64 * P1_WSTR)  // +33792
#define P1_SMEM (P1_WLO + 64 * P1_WSTR)  // 200704

extern "C" __global__ void __launch_bounds__(NTHR, 1)
lstm_gx_kernel(const float* __restrict__ x,
               const float* __restrict__ W,
               const float* __restrict__ bias)
{
    extern __shared__ char smem[];
    const int tid = threadIdx.x;
    const int t   = blockIdx.x;
    const int wid = tid >> 5;
    const int lid = tid & 31;
    const int grp = lid >> 2;
    const int tg  = lid & 3;
    const int m_base = (wid >> 1) * 16;   // 4 M-groups
    const int n_base = (wid & 1) * 32;    // 2 N-groups

    // stage x_t (64 x 512 fp32) -> bf16 hi/lo SMEM [b][k]
    {
        const float4* x4 = (const float4*)(x + (size_t)t * B_SZ * 512);
        for (int idx = tid; idx < 64 * 128; idx += NTHR) {
            int r  = idx >> 7;
            int c4 = idx & 127;
            float4 v = x4[r * 128 + c4];
            __nv_bfloat16 h0 = __float2bfloat16_rn(v.x);
            __nv_bfloat16 h1 = __float2bfloat16_rn(v.y);
            __nv_bfloat16 h2 = __float2bfloat16_rn(v.z);
            __nv_bfloat16 h3 = __float2bfloat16_rn(v.w);
            int o = r * P1_ASTR + c4 * 8;
            *(__nv_bfloat162*)(smem + P1_AHI + o)     = __nv_bfloat162(h0, h1);
            *(__nv_bfloat162*)(smem + P1_AHI + o + 4) = __nv_bfloat162(h2, h3);
            *(__nv_bfloat162*)(smem + P1_ALO + o) =
                __nv_bfloat162(__float2bfloat16_rn(v.x - __bfloat162float(h0)),
                               __float2bfloat16_rn(v.y - __bfloat162float(h1)));
            *(__nv_bfloat162*)(smem + P1_ALO + o + 4) =
                __nv_bfloat162(__float2bfloat16_rn(v.z - __bfloat162float(h2)),
                               __float2bfloat16_rn(v.w - __bfloat162float(h3)));
        }
    }
    __syncthreads();

    for (int ntile = 0; ntile < 32; ntile++) {
        float acc[4][4];
        #pragma unroll
        for (int i = 0; i < 4; i++) { acc[i][0]=0.f; acc[i][1]=0.f; acc[i][2]=0.f; acc[i][3]=0.f; }

        for (int kc = 0; kc < 2; kc++) {
            __syncthreads();   // previous chunk's GEMM done before W overwrite
            // stage W chunk: rows k in [kc*256,+256), cols [ntile*64,+64)
            {
                const float* wsrc = W + (size_t)(kc * 256) * G4 + ntile * 64;
                for (int idx = tid; idx < 256 * 64; idx += NTHR) {
                    int n = idx & 63;
                    int k = idx >> 6;
                    float w = wsrc[(size_t)k * G4 + n];
                    __nv_bfloat16 hi = __float2bfloat16_rn(w);
                    __nv_bfloat16 lo = __float2bfloat16_rn(w - __bfloat162float(hi));
                    int o = n * P1_WSTR + k * 2;
                    *(__nv_bfloat16*)(smem + P1_WHI + o) = hi;
                    *(__nv_bfloat16*)(smem + P1_WLO + o) = lo;
                }
            }
            __syncthreads();

            const char* arow = smem + (m_base + grp) * P1_ASTR + kc * 512 + tg * 4;
            #pragma unroll 4
            for (int ks = 0; ks < 16; ks++) {
                const int kb = ks * 32;
                uint32_t a_hi[4], a_lo[4];
                a_hi[0] = *(const uint32_t*)(arow + P1_AHI + kb);
                a_hi[1] = *(const uint32_t*)(arow + P1_AHI + 8 * P1_ASTR + kb);
                a_hi[2] = *(const uint32_t*)(arow + P1_AHI + kb + 16);
                a_hi[3] = *(const uint32_t*)(arow + P1_AHI + 8 * P1_ASTR + kb + 16);
                a_lo[0] = *(const uint32_t*)(arow + P1_ALO + kb);
                a_lo[1] = *(const uint32_t*)(arow + P1_ALO + 8 * P1_ASTR + kb);
                a_lo[2] = *(const uint32_t*)(arow + P1_ALO + kb + 16);
                a_lo[3] = *(const uint32_t*)(arow + P1_ALO + 8 * P1_ASTR + kb + 16);
                #pragma unroll
                for (int nt = 0; nt < 4; nt++) {
                    const char* brow = smem + (n_base + nt * 8 + grp) * P1_WSTR + tg * 4 + kb;
                    uint32_t b_hi[2], b_lo[2];
                    b_hi[0] = *(const uint32_t*)(brow + P1_WHI);
                    b_hi[1] = *(const uint32_t*)(brow + P1_WHI + 16);
                    b_lo[0] = *(const uint32_t*)(brow + P1_WLO);
                    b_lo[1] = *(const uint32_t*)(brow + P1_WLO + 16);
                    mma_bf16(acc[nt], a_hi, b_hi);
                    mma_bf16(acc[nt], a_hi, b_lo);
                    mma_bf16(acc[nt], a_lo, b_hi);
                }
            }
        }
        // epilogue: gx[t][col][b] = acc + bias[col]
        #pragma unroll
        for (int nt = 0; nt < 4; nt++) {
            int col = ntile * 64 + n_base + nt * 8 + tg * 2;
            int b0  = m_base + grp;
            float bi0 = bias[col];
            float bi1 = bias[col + 1];
            float* dst = g_gx + ((size_t)t * G4 + col) * B_SZ;
            dst[b0]            = acc[nt][0] + bi0;
            dst[B_SZ + b0]     = acc[nt][1] + bi1;
            dst[b0 + 8]        = acc[nt][2] + bi0;
            dst[B_SZ + b0 + 8] = acc[nt][3] + bi1;
        }
    }
}

// ============================================================================
// Phase 2: persistent recurrent loop. CTA bid owns h-cols [4bid, 4bid+4) and
// gate cols {g*512 + 4bid + jj}. GEMM M64 x N16 x K512: 8 warps = 4M x 2K-halves,
// warp tile M16 x N16; K-halves reduced through SMEM. One grid barrier/step.
// ============================================================================
#define P2_STR  1040
#define P2_AHI  0
#define P2_ALO  (64 * P2_STR)             // 66560
#define P2_WHI  (2 * 64 * P2_STR)         // 133120
#define P2_WLO  (P2_WHI + 16 * P2_STR)    // +16640
#define P2_GH   (P2_WLO + 16 * P2_STR)    // 166400; [kh][n16][b64] fp32 = 8KB
#define P2_SMEM (P2_GH + 8192)            // 174592

__device__ __forceinline__ void grid_barrier(unsigned target) {
    __syncthreads();
    if (threadIdx.x == 0) {
        unsigned* bar = &g_bar;
        asm volatile("red.release.gpu.add.u32 [%0], 1;" :: "l"(bar) : "memory");
        unsigned v;
        do {
            asm volatile("ld.acquire.gpu.u32 %0, [%1];" : "=r"(v) : "l"(bar) : "memory");
        } while (v < target);
    }
    __syncthreads();
}

extern "C" __global__ void __launch_bounds__(NTHR, 1)
lstm_loop_kernel(const float* __restrict__ hidden0,
                 const float* __restrict__ cell0,
                 const float* __restrict__ W,
                 float* __restrict__ out)
{
    extern __shared__ char smem[];
    const int tid = threadIdx.x;
    const int bid = blockIdx.x;
    const int wid = tid >> 5;
    const int lid = tid & 31;
    const int grp = lid >> 2;
    const int tg  = lid & 3;
    const int mg  = wid & 3;     // M-group 0..3
    const int kh  = wid >> 2;    // K-half 0..1

    // elementwise ownership: thread = (jj, b), coalesced along b
    const int jj = tid >> 6;     // 0..3
    const int b  = tid & 63;
    const int ej = bid * 4 + jj; // global h column

    // ---- init: Wh slice -> SMEM [n16][k512] hi/lo; n = g*4 + jj' ----
    for (int idx = tid; idx < 16 * 512; idx += NTHR) {
        int n = idx & 15;
        int k = idx >> 4;
        float w = W[(size_t)(512 + k) * G4 + (n >> 2) * H_SZ + bid * 4 + (n & 3)];
        __nv_bfloat16 hi = __float2bfloat16_rn(w);
        __nv_bfloat16 lo = __float2bfloat16_rn(w - __bfloat162float(hi));
        int o = n * P2_STR + k * 2;
        *(__nv_bfloat16*)(smem + P2_WHI + o) = hi;
        *(__nv_bfloat16*)(smem + P2_WLO + o) = lo;
    }
    // h state init (owner writes its 4 columns)
    float c_state = cell0[b * H_SZ + ej];
    {
        float hv = hidden0[b * H_SZ + ej];
        __nv_bfloat16 hh = __float2bfloat16_rn(hv);
        g_h_hi[b * H_SZ + ej] = hh;
        g_h_lo[b * H_SZ + ej] = __float2bfloat16_rn(hv - __bfloat162float(hh));
    }
    float h_last = 0.0f;

    // prefetch gx for t=0
    float gxp[4];
    {
        const float* src = g_gx + (size_t)(0 * G4 + bid * 4 + jj) * B_SZ + b;
        #pragma unroll
        for (int g = 0; g < 4; g++) gxp[g] = src[(size_t)g * H_SZ * B_SZ];
    }

    unsigned bar_n = 1;
    grid_barrier(NCTA * bar_n); bar_n++;

    for (int t = 0; t < T_STEPS; t++) {
        // ---- stage h (64 x 512) hi/lo -> SMEM [b][k] ----
        for (int idx = tid; idx < 64 * 64; idx += NTHR) {
            int r   = idx >> 6;
            int c16 = idx & 63;
            uint4 vh = *(const uint4*)(g_h_hi + r * 512 + c16 * 8);
            uint4 vl = *(const uint4*)(g_h_lo + r * 512 + c16 * 8);
            int o = r * P2_STR + c16 * 16;
            *(uint4*)(smem + P2_AHI + o) = vh;
            *(uint4*)(smem + P2_ALO + o) = vl;
        }
        __syncthreads();

        // ---- GEMM: warp (mg, kh): rows [mg*16,+16) x 16 cols x K[kh*256,+256) ----
        float acc[2][4];
        acc[0][0]=0.f; acc[0][1]=0.f; acc[0][2]=0.f; acc[0][3]=0.f;
        acc[1][0]=0.f; acc[1][1]=0.f; acc[1][2]=0.f; acc[1][3]=0.f;
        {
            const char* arow = smem + (mg * 16 + grp) * P2_STR + kh * 512 + tg * 4;
            const char* bbase = smem + kh * 512 + tg * 4;
            #pragma unroll 4
            for (int ks = 0; ks < 16; ks++) {
                const int kb = ks * 32;
                uint32_t a_hi[4], a_lo[4];
                a_hi[0] = *(const uint32_t*)(arow + P2_AHI + kb);
                a_hi[1] = *(const uint32_t*)(arow + P2_AHI + 8 * P2_STR + kb);
                a_hi[2] = *(const uint32_t*)(arow + P2_AHI + kb + 16);
                a_hi[3] = *(const uint32_t*)(arow + P2_AHI + 8 * P2_STR + kb + 16);
                a_lo[0] = *(const uint32_t*)(arow + P2_ALO + kb);
                a_lo[1] = *(const uint32_t*)(arow + P2_ALO + 8 * P2_STR + kb);
                a_lo[2] = *(const uint32_t*)(arow + P2_ALO + kb + 16);
                a_lo[3] = *(const uint32_t*)(arow + P2_ALO + 8 * P2_STR + kb + 16);
                #pragma unroll
                for (int nt = 0; nt < 2; nt++) {
                    const char* brow = bbase + (nt * 8 + grp) * P2_STR + kb;
                    uint32_t b_hi[2], b_lo[2];
                    b_hi[0] = *(const uint32_t*)(brow + P2_WHI);
                    b_hi[1] = *(const uint32_t*)(brow + P2_WHI + 16);
                    b_lo[0] = *(const uint32_t*)(brow + P2_WLO);
                    b_lo[1] = *(const uint32_t*)(brow + P2_WLO + 16);
                    mma_bf16(acc[nt], a_hi, b_hi);
                    mma_bf16(acc[nt], a_hi, b_lo);
                    mma_bf16(acc[nt], a_lo, b_hi);
                }
            }
        }
        // store partial gh to SMEM: [kh][n][b] fp32
        {
            float* gh = (float*)(smem + P2_GH) + kh * 16 * 64;
            #pragma unroll
            for (int nt = 0; nt < 2; nt++) {
                int n  = nt * 8 + tg * 2;
                int b0 = mg * 16 + grp;
                gh[n * 64 + b0]           = acc[nt][0];
                gh[(n + 1) * 64 + b0]     = acc[nt][1];
                gh[n * 64 + b0 + 8]       = acc[nt][2];
                gh[(n + 1) * 64 + b0 + 8] = acc[nt][3];
            }
        }
        __syncthreads();

        // ---- local elementwise ----
        {
            const float* gh0 = (const float*)(smem + P2_GH);
            const float* gh1 = gh0 + 16 * 64;
            float g0 = gh0[(0 * 4 + jj) * 64 + b] + gh1[(0 * 4 + jj) * 64 + b] + gxp[0];
            float g1 = gh0[(1 * 4 + jj) * 64 + b] + gh1[(1 * 4 + jj) * 64 + b] + gxp[1];
            float g2 = gh0[(2 * 4 + jj) * 64 + b] + gh1[(2 * 4 + jj) * 64 + b] + gxp[2];
            float g3 = gh0[(3 * 4 + jj) * 64 + b] + gh1[(3 * 4 + jj) * 64 + b] + gxp[3];
            float f  = sigmoidf_fast(g0);
            float ii = sigmoidf_fast(g1);
            float cd = tanhf_fast(g2);
            float o  = sigmoidf_fast(g3);
            c_state = f * c_state + ii * cd;
            float h = o * tanhf_fast(c_state);
            h_last = h;
            out[(size_t)t * (B_SZ * H_SZ) + b * H_SZ + ej] = h;
            __nv_bfloat16 hh = __float2bfloat16_rn(h);
            g_h_hi[b * H_SZ + ej] = hh;
            g_h_lo[b * H_SZ + ej] = __float2bfloat16_rn(h - __bfloat162float(hh));
            // prefetch gx for t+1 (clamped; off critical path)
            int tn = (t + 1 < T_STEPS) ? t + 1 : t;
            const float* src = g_gx + (size_t)(tn * G4 + bid * 4 + jj) * B_SZ + b;
            #pragma unroll
            for (int g = 0; g < 4; g++) gxp[g] = src[(size_t)g * H_SZ * B_SZ];
        }

        grid_barrier(NCTA * bar_n); bar_n++;
    }

    // final states
    {
        size_t base = (size_t)T_STEPS * B_SZ * H_SZ;
        out[base + b * H_SZ + ej] = h_last;
        out[base + B_SZ * H_SZ + b * H_SZ + ej] = c_state;
    }
}

// ============================================================================
extern "C" void kernel_launch(void* const* d_in, const int* in_sizes, int n_in,
                              void* d_out, int out_size)
{
    (void)in_sizes; (void)n_in; (void)out_size;
    const float* x       = (const float*)d_in[0];
    const float* hidden0 = (const float*)d_in[1];
    const float* cell0   = (const float*)d_in[2];
    const float* W       = (const float*)d_in[3];
    const float* bias    = (const float*)d_in[4];
    float* out = (float*)d_out;

    void* bar_addr = nullptr;
    cudaGetSymbolAddress(&bar_addr, g_bar);
    cudaMemsetAsync(bar_addr, 0, sizeof(unsigned));

    cudaFuncSetAttribute(lstm_gx_kernel,
                         cudaFuncAttributeMaxDynamicSharedMemorySize, P1_SMEM);
    cudaFuncSetAttribute(lstm_loop_kernel,
                         cudaFuncAttributeMaxDynamicSharedMemorySize, P2_SMEM);

    lstm_gx_kernel<<<T_STEPS, NTHR, P1_SMEM>>>(x, W, bias);
    lstm_loop_kernel<<<NCTA, NTHR, P2_SMEM>>>(hidden0, cell0, W, out);
}